// round 1
// baseline (speedup 1.0000x reference)
#include <cuda_runtime.h>
#include <math.h>

// Problem constants
#define EMBED 1024
#define NHEAD 16
#define HD    64
#define BATCH 4
#define SEQ   2048

// Scratch: Q/K/V in [sel][b][h][t][d] layout, fp32.
// 3 * 4 * 16 * 2048 * 64 floats = 100.7 MB (static __device__ array: allowed).
__device__ float g_qkv[(size_t)3 * BATCH * NHEAD * SEQ * HD];

// ---------------------------------------------------------------------------
// Kernel 1: QKV projection.  qkv[m, n] = sum_k x[m,k] * W[n,k] + b[n]
// M = B*T = 8192, N = 3*C = 3072, K = C = 1024.  Both A and B are K-major
// row-major, so this is A * B^T with coalesced K-axis loads for both.
// Output written directly into [sel][b][h][t][d] layout; Q pre-scaled by
// 1/sqrt(hd) = 0.125 (fold the softmax scale into the projection).
// ---------------------------------------------------------------------------
__global__ __launch_bounds__(256, 2)
void qkv_gemm_kernel(const float* __restrict__ x,
                     const float* __restrict__ W,
                     const float* __restrict__ bias)
{
    constexpr int BM = 128, BN = 128, BK = 16;
    __shared__ float As[BK][BM + 4];   // [k][m], stride 132 (16B-aligned rows)
    __shared__ float Bs[BK][BN + 4];   // [k][n]

    const int tid = threadIdx.x;            // 256 threads
    const int bm  = blockIdx.y * BM;
    const int bn  = blockIdx.x * BN;

    // global-load mapping: 64 rows x 16 k per pass, 2 passes
    const int lr = tid >> 2;                // 0..63
    const int lc = (tid & 3) << 2;          // 0,4,8,12

    // compute mapping: 16x16 thread grid, 8x8 microtile
    const int ty = tid >> 4;                // 0..15
    const int tx = tid & 15;                // 0..15

    float acc[8][8];
#pragma unroll
    for (int i = 0; i < 8; ++i)
#pragma unroll
        for (int j = 0; j < 8; ++j) acc[i][j] = 0.f;

    const float* xA = x + (size_t)(bm + lr) * EMBED + lc;
    const float* wB = W + (size_t)(bn + lr) * EMBED + lc;

    for (int k0 = 0; k0 < EMBED; k0 += BK) {
#pragma unroll
        for (int h = 0; h < 2; ++h) {
            float4 a = *(const float4*)(xA + (size_t)h * 64 * EMBED + k0);
            As[lc + 0][lr + h * 64] = a.x;
            As[lc + 1][lr + h * 64] = a.y;
            As[lc + 2][lr + h * 64] = a.z;
            As[lc + 3][lr + h * 64] = a.w;
            float4 b = *(const float4*)(wB + (size_t)h * 64 * EMBED + k0);
            Bs[lc + 0][lr + h * 64] = b.x;
            Bs[lc + 1][lr + h * 64] = b.y;
            Bs[lc + 2][lr + h * 64] = b.z;
            Bs[lc + 3][lr + h * 64] = b.w;
        }
        __syncthreads();

#pragma unroll
        for (int k = 0; k < BK; ++k) {
            float a[8], b[8];
            *(float4*)&a[0] = *(const float4*)&As[k][ty * 8];
            *(float4*)&a[4] = *(const float4*)&As[k][ty * 8 + 4];
            *(float4*)&b[0] = *(const float4*)&Bs[k][tx * 4];
            *(float4*)&b[4] = *(const float4*)&Bs[k][64 + tx * 4];
#pragma unroll
            for (int i = 0; i < 8; ++i)
#pragma unroll
                for (int j = 0; j < 8; ++j)
                    acc[i][j] += a[i] * b[j];
        }
        __syncthreads();
    }

    // Epilogue: bias, Q-scale, scatter to [sel][b][h][t][d]
#pragma unroll
    for (int jg = 0; jg < 2; ++jg) {
        const int n4  = bn + jg * 64 + tx * 4;   // 4-aligned, never crosses a head
        const int sel = n4 >> 10;                // 0=Q, 1=K, 2=V
        const int nn  = n4 & 1023;
        const int hh  = nn >> 6;
        const int dd  = nn & 63;
        const float scale = (sel == 0) ? 0.125f : 1.0f;
        float4 bv = *(const float4*)(bias + n4);
#pragma unroll
        for (int i = 0; i < 8; ++i) {
            const int m = bm + ty * 8 + i;
            const int b = m >> 11;               // m / SEQ
            const int t = m & (SEQ - 1);
            float4 v;
            v.x = (acc[i][jg * 4 + 0] + bv.x) * scale;
            v.y = (acc[i][jg * 4 + 1] + bv.y) * scale;
            v.z = (acc[i][jg * 4 + 2] + bv.z) * scale;
            v.w = (acc[i][jg * 4 + 3] + bv.w) * scale;
            const size_t off =
                ((((size_t)sel * BATCH + b) * NHEAD + hh) * SEQ + t) * HD + dd;
            *(float4*)(g_qkv + off) = v;
        }
    }
}

// ---------------------------------------------------------------------------
// Kernel 2: causal flash attention, fp32.
// Grid: (T/64, B*H).  Block: 256 threads.  Each block: 64 query rows,
// iterates K/V in 32-row tiles up to the causal boundary.
// Thread (r = tid/4, g = tid%4): 4 threads per query row.
//   - score phase: thread owns columns c = g + 4j (j<8)   -> conflict-free Ks
//   - output phase: thread owns dims   d = 16jj + 4g (jj<4) -> conflict-free Vs,
//     coalesced y stores.
// Row max/sum reduced across the quad with __shfl_xor (lanes g, g^1, g^2).
// ---------------------------------------------------------------------------
__global__ __launch_bounds__(256, 2)
void attn_kernel(float* __restrict__ y)
{
    __shared__ float Qs[64][68];   // pad 68: rows 4 banks apart, 16B-aligned
    __shared__ float Ks[32][68];
    __shared__ float Vs[32][68];
    __shared__ float Ps[64][36];   // scalar access only; pad 36 ≡ 4 mod 32

    const int tid = threadIdx.x;
    const int qb  = blockIdx.x;          // 0..31 query block
    const int bh  = blockIdx.y;          // 0..63 (b*16 + h)
    const int r   = tid >> 2;            // query row in block, 0..63
    const int g   = tid & 3;             // quad lane

    const float* Qg = g_qkv + ((size_t)bh * SEQ + qb * 64) * HD;     // sel 0
    const float* Kg = g_qkv + ((size_t)(64 + bh) * SEQ) * HD;        // sel 1
    const float* Vg = g_qkv + ((size_t)(128 + bh) * SEQ) * HD;       // sel 2

    // Load Q tile (64 x 64)
    {
        const int row = tid >> 4;                 // 0..15
        const int col = (tid & 15) << 2;          // 0..60
#pragma unroll
        for (int rr = 0; rr < 4; ++rr) {
            float4 v = *(const float4*)(Qg + (size_t)(row + rr * 16) * HD + col);
            *(float4*)&Qs[row + rr * 16][col] = v;
        }
    }

    const float NEG = -1e30f;
    float m = NEG, l = 0.f;
    float4 o[4];
#pragma unroll
    for (int jj = 0; jj < 4; ++jj) o[jj] = make_float4(0.f, 0.f, 0.f, 0.f);

    const int qrow   = qb * 64 + r;
    const int ntiles = 2 * qb + 2;
    const int kr = tid >> 3;             // 0..31 (K/V load row)
    const int kc = (tid & 7) << 3;       // 0..56

    for (int kt = 0; kt < ntiles; ++kt) {
        // Load K,V tiles (32 x 64 each)
        {
            const float* kp = Kg + (size_t)(kt * 32 + kr) * HD + kc;
            const float* vp = Vg + (size_t)(kt * 32 + kr) * HD + kc;
            *(float4*)&Ks[kr][kc]     = *(const float4*)(kp);
            *(float4*)&Ks[kr][kc + 4] = *(const float4*)(kp + 4);
            *(float4*)&Vs[kr][kc]     = *(const float4*)(vp);
            *(float4*)&Vs[kr][kc + 4] = *(const float4*)(vp + 4);
        }
        __syncthreads();

        // --- Phase A: scores s[j] = Q[r,:] . K[g+4j,:]  (Q pre-scaled) ---
        float s[8];
#pragma unroll
        for (int j = 0; j < 8; ++j) s[j] = 0.f;
#pragma unroll
        for (int d0 = 0; d0 < HD; d0 += 4) {
            const float4 q4 = *(const float4*)&Qs[r][d0];
#pragma unroll
            for (int j = 0; j < 8; ++j) {
                const float4 k4 = *(const float4*)&Ks[g + 4 * j][d0];
                s[j] += q4.x * k4.x + q4.y * k4.y + q4.z * k4.z + q4.w * k4.w;
            }
        }

        // Causal mask only needed on the last two tiles of each q-block
        if (kt >= 2 * qb) {
#pragma unroll
            for (int j = 0; j < 8; ++j) {
                const int c = kt * 32 + g + 4 * j;
                if (c > qrow) s[j] = NEG;
            }
        }

        // Online softmax (quad reduction)
        float mx = s[0];
#pragma unroll
        for (int j = 1; j < 8; ++j) mx = fmaxf(mx, s[j]);
        mx = fmaxf(mx, __shfl_xor_sync(0xffffffffu, mx, 1));
        mx = fmaxf(mx, __shfl_xor_sync(0xffffffffu, mx, 2));
        const float m_new = fmaxf(m, mx);
        const float corr  = __expf(m - m_new);     // 0 on first tile
        float sum = 0.f;
#pragma unroll
        for (int j = 0; j < 8; ++j) {
            const float p = __expf(s[j] - m_new);  // underflows to 0 when masked
            Ps[r][g + 4 * j] = p;
            sum += p;
        }
        sum += __shfl_xor_sync(0xffffffffu, sum, 1);
        sum += __shfl_xor_sync(0xffffffffu, sum, 2);
        l = l * corr + sum;
        m = m_new;
#pragma unroll
        for (int jj = 0; jj < 4; ++jj) {
            o[jj].x *= corr; o[jj].y *= corr; o[jj].z *= corr; o[jj].w *= corr;
        }
        __syncthreads();   // Ps visible, phase A done with Ks

        // --- Phase B: O[r, 16jj+4g .. +3] += sum_c P[r,c] * V[c, d] ---
#pragma unroll 4
        for (int c = 0; c < 32; ++c) {
            const float p = Ps[r][c];
#pragma unroll
            for (int jj = 0; jj < 4; ++jj) {
                const float4 v4 = *(const float4*)&Vs[c][jj * 16 + g * 4];
                o[jj].x += p * v4.x; o[jj].y += p * v4.y;
                o[jj].z += p * v4.z; o[jj].w += p * v4.w;
            }
        }
        __syncthreads();   // done with Ps/Vs before next tile overwrites
    }

    // Normalize and store y[b, t, h*64 + d]
    const float inv = 1.0f / l;
    const int b = bh >> 4;
    const int h = bh & 15;
    float* yp = y + ((size_t)b * SEQ + qb * 64 + r) * EMBED + h * HD;
#pragma unroll
    for (int jj = 0; jj < 4; ++jj) {
        float4 v;
        v.x = o[jj].x * inv; v.y = o[jj].y * inv;
        v.z = o[jj].z * inv; v.w = o[jj].w * inv;
        *(float4*)(yp + jj * 16 + g * 4) = v;
    }
}

// ---------------------------------------------------------------------------
extern "C" void kernel_launch(void* const* d_in, const int* in_sizes, int n_in,
                              void* d_out, int out_size)
{
    const float* x    = (const float*)d_in[0];   // [4, 2048, 1024]
    const float* W    = (const float*)d_in[1];   // [3072, 1024]
    const float* bias = (const float*)d_in[2];   // [3072]
    float* y = (float*)d_out;                    // [4, 2048, 1024]

    dim3 gemm_grid(3072 / 128, 8192 / 128);      // (24, 64)
    qkv_gemm_kernel<<<gemm_grid, 256>>>(x, W, bias);

    dim3 attn_grid(SEQ / 64, BATCH * NHEAD);     // (32, 64)
    attn_kernel<<<attn_grid, 256>>>(y);
}